// round 12
// baseline (speedup 1.0000x reference)
#include <cuda_runtime.h>
#include <stdint.h>

// Problem constants (from reference)
#define MASS_H2O   18.01056f
#define MASS_NH3   17.02655f
#define MAX_MZ     30000
#define WINDOW     10
#define VOCAB      26
#define BATCH      32768
#define IONS       8

#define TOTAL_GROUPS     (BATCH * VOCAB)               // 851,968
#define TILE_GROUPS      512
#define NUM_TILES        (TOTAL_GROUPS / TILE_GROUPS)  // 1664 exactly
#define WINDOWS_PER_TILE (TILE_GROUPS * IONS)          // 4096
#define ELEMS_PER_TILE   (WINDOWS_PER_TILE * WINDOW)   // 40960
#define VEC2_PER_TILE    (ELEMS_PER_TILE / 2)          // 20480
#define THREADS          1024
#define VEC2_PER_WARP    (VEC2_PER_TILE / 32)          // 640
#define K_PER_WARP       (VEC2_PER_WARP / 32)          // 20 float2 per thread
#define BATCH_N          10                            // metas prefetched per batch

#define SPEC_FLOATS_PAD  30016                  // 30000 + 16 zero pad
#define SPEC_BYTES       (SPEC_FLOATS_PAD * 4)  // 120,064
#define META_BYTES       (WINDOWS_PER_TILE * 4) // SINGLE buffer: 16,384
#define SMEM_BYTES       (SPEC_BYTES + META_BYTES)     // 136,448

#define ZERO_IDX    30000                       // points at zero pad
#define GRID_BLOCKS 152

// One ion-variant window base from c (already cb or cy). EXACT reference
// arithmetic: variant first (single rounding), then *10, round-half-even.
__device__ __forceinline__
int one_meta(float c, int jj, bool vok)
{
    float m;
    if      (jj == 1) m = c - MASS_H2O;
    else if (jj == 2) m = c - MASS_NH3;
    else if (jj == 3) m = c * 0.5f;
    else              m = c;
    const int  idx  = __float2int_rn(m * 10.0f) - (WINDOW / 2);
    const bool keep = (idx >= 0) && (idx <= MAX_MZ - WINDOW) && vok;
    return keep ? idx : ZERO_IDX;
}

__global__ void __launch_bounds__(THREADS, 1)
intensity_kernel(const float* __restrict__ pepmass,
                 const float* __restrict__ prefix_mass,
                 const float* __restrict__ masses,
                 const float* __restrict__ spectrum,
                 const int*   __restrict__ dir_ptr,
                 float* __restrict__ out)
{
    extern __shared__ unsigned char smem_raw[];
    float* spec = reinterpret_cast<float*>(smem_raw);
    int*   mb   = reinterpret_cast<int*>(smem_raw + SPEC_BYTES);

    const int tid  = threadIdx.x;
    const int lane = tid & 31;
    const int warp = tid >> 5;
    const int dir  = dir_ptr ? __ldg(dir_ptr) : 0;
    const int gl   = tid >> 1;          // group within tile owned by thread
    const int half = tid & 1;           // 0 -> ions 0..3 (cb), 1 -> ions 4..7 (cy)

    // ---- stage spectrum into SMEM (zero the 16-float pad) ----
    {
        const float4* s4 = reinterpret_cast<const float4*>(spectrum);
        float4*       d4 = reinterpret_cast<float4*>(spec);
        const float4  z4 = make_float4(0.f, 0.f, 0.f, 0.f);
        #pragma unroll 2
        for (int i = tid; i < SPEC_FLOATS_PAD / 4; i += THREADS)
            d4[i] = (i < MAX_MZ / 4) ? s4[i] : z4;
    }

    // ---- prologue: prefetch tile-0 inputs (3 LDGs per thread) ----
    float pm, pf, ms;
    int   v;
    {
        const int g = blockIdx.x * TILE_GROUPS + gl;
        const int b = g / VOCAB;  v = g - b * VOCAB;
        pm = __ldg(pepmass + b); pf = __ldg(prefix_mass + b); ms = __ldg(masses + v);
    }

    __syncthreads();   // spectrum staged; after this, warps are independent:
                       // warp w writes meta windows [128w,128w+128) and reads
                       // ONLY those windows in phase 2 -> __syncwarp suffices.

    const int qwarp = warp * VEC2_PER_WARP;   // warp's first float2 in a tile

    for (int tile = blockIdx.x; tile < NUM_TILES; tile += GRID_BLOCKS) {

        // ---- phase 1: this thread's 4 windows, one STS.128 ----
        {
            float cb, cy;
            if (dir == 0) { cb = pf + ms; cy = pm - cb; }
            else          { cy = pf + ms; cb = pm - cy; }
            const float c   = half ? cy : cb;
            const bool  vok = (v >= 3);
            int4 mw;
            mw.x = one_meta(c, 0, vok);
            mw.y = one_meta(c, 1, vok);
            mw.z = one_meta(c, 2, vok);
            mw.w = one_meta(c, 3, vok);
            reinterpret_cast<int4*>(mb)[tid] = mw;   // windows 4*tid..4*tid+3
        }
        __syncwarp();      // meta visible warp-wide (warp-private region)

        // ---- issue NEXT tile's 3 loads; consumers only at next loop top ----
        {
            int nt = tile + GRID_BLOCKS;
            if (nt >= NUM_TILES) nt = tile;          // clamp: harmless reload
            const int g = nt * TILE_GROUPS + gl;
            const int b = g / VOCAB;  v = g - b * VOCAB;
            pm = __ldg(pepmass + b); pf = __ldg(prefix_mass + b); ms = __ldg(masses + v);
        }

        // ---------- Phase 2: 20 float2 per thread, batched meta prefetch ----
        // Warp w covers float2 q in [640w, 640w+640): reads windows q/5 in
        // [128w, 128w+128) == the windows this warp just wrote.
        // A float2 at even element offset NEVER straddles a window.
        float2* out2 = reinterpret_cast<float2*>(out) + tile * VEC2_PER_TILE;

        #pragma unroll
        for (int kk = 0; kk < K_PER_WARP / BATCH_N; ++kk) {
            int addr[BATCH_N];

            #pragma unroll
            for (int j = 0; j < BATCH_N; ++j) {
                const int q = qwarp + (kk * BATCH_N + j) * 32 + lane;
                const unsigned win = (unsigned)q / 5u;   // window = (2q)/10
                const int w0 = (q - (int)win * 5) * 2;   // in {0,2,4,6,8}
                addr[j] = mb[win] + w0;                  // LDS.32 meta burst
            }

            #pragma unroll
            for (int j = 0; j < BATCH_N; ++j) {
                const int q = qwarp + (kk * BATCH_N + j) * 32 + lane;
                float2 o;
                o.x = spec[addr[j]];
                o.y = spec[addr[j] + 1];
                __stcs(out2 + q, o);                     // streaming STG.64
            }
        }
        __syncwarp();      // all reads done before next tile's STS overwrite
    }
}

extern "C" void kernel_launch(void* const* d_in, const int* in_sizes, int n_in,
                              void* d_out, int out_size)
{
    const float* spectrum    = (const float*)d_in[0];
    const float* pepmass     = (const float*)d_in[1];
    const float* prefix_mass = (const float*)d_in[2];
    const float* masses      = (const float*)d_in[3];
    const int*   dir_ptr     = (n_in >= 5) ? (const int*)d_in[4] : nullptr;
    float*       out         = (float*)d_out;

    cudaFuncSetAttribute(intensity_kernel,
                         cudaFuncAttributeMaxDynamicSharedMemorySize, SMEM_BYTES);

    intensity_kernel<<<GRID_BLOCKS, THREADS, SMEM_BYTES>>>(
        pepmass, prefix_mass, masses, spectrum, dir_ptr, out);
}

// round 13
// speedup vs baseline: 1.1074x; 1.1074x over previous
#include <cuda_runtime.h>
#include <stdint.h>

// Problem constants (from reference)
#define MASS_H2O   18.01056f
#define MASS_NH3   17.02655f
#define MAX_MZ     30000
#define WINDOW     10
#define VOCAB      26
#define BATCH      32768
#define IONS       8

#define TOTAL_GROUPS     (BATCH * VOCAB)               // 851,968
#define TILE_GROUPS      512
#define NUM_TILES        (TOTAL_GROUPS / TILE_GROUPS)  // 1664 exactly
#define WINDOWS_PER_TILE (TILE_GROUPS * IONS)          // 4096
#define ELEMS_PER_TILE   (WINDOWS_PER_TILE * WINDOW)   // 40960
#define VEC2_PER_TILE    (ELEMS_PER_TILE / 2)          // 20480
#define THREADS          1024
#define VEC2_PER_THREAD  (VEC2_PER_TILE / THREADS)     // 20
#define BATCH_N          5                             // per-batch MLP depth

#define SPEC_FLOATS_PAD  30016                  // 30000 + 16 zero pad
#define SPEC_BYTES       (SPEC_FLOATS_PAD * 4)  // 120,064
#define METABUF          (WINDOWS_PER_TILE + 4)
#define META_BYTES       (2 * METABUF * 4)      // double buffer: 32,800
#define SMEM_BYTES       (SPEC_BYTES + META_BYTES)     // 152,864

#define ZERO_IDX    30000                       // points at zero pad
#define GRID_BLOCKS 152

// One ion-variant window base from c (already cb or cy). EXACT reference
// arithmetic: variant first (single rounding), then *10, round-half-even.
__device__ __forceinline__
int one_meta(float c, int jj, bool vok)
{
    float m;
    if      (jj == 1) m = c - MASS_H2O;
    else if (jj == 2) m = c - MASS_NH3;
    else if (jj == 3) m = c * 0.5f;
    else              m = c;
    const int  idx  = __float2int_rn(m * 10.0f) - (WINDOW / 2);
    const bool keep = (idx >= 0) && (idx <= MAX_MZ - WINDOW) && vok;
    return keep ? idx : ZERO_IDX;
}

__global__ void __launch_bounds__(THREADS, 1)
intensity_kernel(const float* __restrict__ pepmass,
                 const float* __restrict__ prefix_mass,
                 const float* __restrict__ masses,
                 const float* __restrict__ spectrum,
                 const int*   __restrict__ dir_ptr,
                 float* __restrict__ out)
{
    extern __shared__ unsigned char smem_raw[];
    float* spec = reinterpret_cast<float*>(smem_raw);
    int*   meta = reinterpret_cast<int*>(smem_raw + SPEC_BYTES);

    const int tid  = threadIdx.x;
    const int dir  = dir_ptr ? __ldg(dir_ptr) : 0;
    const int gl   = tid >> 1;          // group within tile owned by thread
    const int half = tid & 1;           // 0 -> ions 0..3 (cb), 1 -> ions 4..7 (cy)

    // ---- stage spectrum into SMEM (zero the 16-float pad) ----
    {
        const float4* s4 = reinterpret_cast<const float4*>(spectrum);
        float4*       d4 = reinterpret_cast<float4*>(spec);
        const float4  z4 = make_float4(0.f, 0.f, 0.f, 0.f);
        #pragma unroll 2
        for (int i = tid; i < SPEC_FLOATS_PAD / 4; i += THREADS)
            d4[i] = (i < MAX_MZ / 4) ? s4[i] : z4;
    }

    // ---- prologue: prefetch tile-0 inputs (3 LDGs per thread) ----
    float pm, pf, ms;
    int   v;
    {
        const int g = blockIdx.x * TILE_GROUPS + gl;
        const int b = g / VOCAB;  v = g - b * VOCAB;
        pm = __ldg(pepmass + b); pf = __ldg(prefix_mass + b); ms = __ldg(masses + v);
    }

    int parity = 0;
    for (int tile = blockIdx.x; tile < NUM_TILES; tile += GRID_BLOCKS) {
        int* mb = meta + parity * METABUF;
        parity ^= 1;

        // ---- publish this tile's metadata: 4 windows, one STS.128 ----
        {
            float cb, cy;
            if (dir == 0) { cb = pf + ms; cy = pm - cb; }
            else          { cy = pf + ms; cb = pm - cy; }
            const float c   = half ? cy : cb;
            const bool  vok = (v >= 3);
            int4 mw;
            mw.x = one_meta(c, 0, vok);
            mw.y = one_meta(c, 1, vok);
            mw.z = one_meta(c, 2, vok);
            mw.w = one_meta(c, 3, vok);
            reinterpret_cast<int4*>(mb)[tid] = mw;   // windows 4*tid..4*tid+3
        }
        __syncthreads();   // (first iteration: also covers spectrum staging)

        // ---- issue NEXT tile's 3 loads; consumers only at next loop top ----
        {
            int nt = tile + GRID_BLOCKS;
            if (nt >= NUM_TILES) nt = tile;          // clamp: harmless reload
            const int g = nt * TILE_GROUPS + gl;
            const int b = g / VOCAB;  v = g - b * VOCAB;
            pm = __ldg(pepmass + b); pf = __ldg(prefix_mass + b); ms = __ldg(masses + v);
        }

        // ---------- Phase 2: 20 float2 per thread, 3-stage batches ----------
        // A float2 at even element offset NEVER straddles a window.
        // Stage 1: BATCH_N meta LDS -> addr[]   (independent burst)
        // Stage 2: 2*BATCH_N gather LDS -> v[]  (independent burst, MLP=10)
        // Stage 3: BATCH_N streaming stores.
        float2* out2 = reinterpret_cast<float2*>(out) + tile * VEC2_PER_TILE;

        #pragma unroll
        for (int kk = 0; kk < VEC2_PER_THREAD / BATCH_N; ++kk) {
            int addr[BATCH_N];

            #pragma unroll
            for (int j = 0; j < BATCH_N; ++j) {
                const int q = tid + (kk * BATCH_N + j) * THREADS;
                const unsigned win = (unsigned)q / 5u;   // window = (2q)/10
                const int w0 = (q - (int)win * 5) * 2;   // in {0,2,4,6,8}
                addr[j] = mb[win] + w0;                  // LDS.32 meta burst
            }

            float2 val[BATCH_N];
            #pragma unroll
            for (int j = 0; j < BATCH_N; ++j) {
                val[j].x = spec[addr[j]];
                val[j].y = spec[addr[j] + 1];
            }

            #pragma unroll
            for (int j = 0; j < BATCH_N; ++j) {
                const int q = tid + (kk * BATCH_N + j) * THREADS;
                __stcs(out2 + q, val[j]);                // streaming STG.64
            }
        }
        // no trailing sync: double-buffered metadata (the barrier above
        // proves all readers of the other buffer finished before rewrite)
    }
}

extern "C" void kernel_launch(void* const* d_in, const int* in_sizes, int n_in,
                              void* d_out, int out_size)
{
    const float* spectrum    = (const float*)d_in[0];
    const float* pepmass     = (const float*)d_in[1];
    const float* prefix_mass = (const float*)d_in[2];
    const float* masses      = (const float*)d_in[3];
    const int*   dir_ptr     = (n_in >= 5) ? (const int*)d_in[4] : nullptr;
    float*       out         = (float*)d_out;

    cudaFuncSetAttribute(intensity_kernel,
                         cudaFuncAttributeMaxDynamicSharedMemorySize, SMEM_BYTES);

    intensity_kernel<<<GRID_BLOCKS, THREADS, SMEM_BYTES>>>(
        pepmass, prefix_mass, masses, spectrum, dir_ptr, out);
}

// round 14
// speedup vs baseline: 1.1082x; 1.0007x over previous
#include <cuda_runtime.h>
#include <stdint.h>

// Problem constants (from reference)
#define MASS_H2O   18.01056f
#define MASS_NH3   17.02655f
#define MAX_MZ     30000
#define WINDOW     10
#define VOCAB      26
#define BATCH      32768
#define IONS       8

#define TOTAL_GROUPS     (BATCH * VOCAB)               // 851,968
#define TILE_GROUPS      512
#define NUM_TILES        (TOTAL_GROUPS / TILE_GROUPS)  // 1664 exactly
#define WINDOWS_PER_TILE (TILE_GROUPS * IONS)          // 4096
#define ELEMS_PER_TILE   (WINDOWS_PER_TILE * WINDOW)   // 40960
#define VEC2_PER_TILE    (ELEMS_PER_TILE / 2)          // 20480
#define THREADS          1024
#define VEC2_PER_THREAD  (VEC2_PER_TILE / THREADS)     // 20
#define ABATCH           10                            // meta MLP depth
#define VBATCH           5                             // value sub-batch

#define SPEC_FLOATS_PAD  30016                  // 30000 + 16 zero pad
#define SPEC_BYTES       (SPEC_FLOATS_PAD * 4)  // 120,064
#define METABUF          (WINDOWS_PER_TILE + 4)
#define META_BYTES       (2 * METABUF * 4)      // double buffer: 32,800
#define SMEM_BYTES       (SPEC_BYTES + META_BYTES)     // 152,864

#define ZERO_IDX    30000                       // points at zero pad
#define GRID_BLOCKS 152

// One ion-variant window base from c (already cb or cy). EXACT reference
// arithmetic: variant first (single rounding), then *10, round-half-even.
__device__ __forceinline__
int one_meta(float c, int jj, bool vok)
{
    float m;
    if      (jj == 1) m = c - MASS_H2O;
    else if (jj == 2) m = c - MASS_NH3;
    else if (jj == 3) m = c * 0.5f;
    else              m = c;
    const int  idx  = __float2int_rn(m * 10.0f) - (WINDOW / 2);
    const bool keep = (idx >= 0) && (idx <= MAX_MZ - WINDOW) && vok;
    return keep ? idx : ZERO_IDX;
}

__global__ void __launch_bounds__(THREADS, 1)
intensity_kernel(const float* __restrict__ pepmass,
                 const float* __restrict__ prefix_mass,
                 const float* __restrict__ masses,
                 const float* __restrict__ spectrum,
                 const int*   __restrict__ dir_ptr,
                 float* __restrict__ out)
{
    extern __shared__ unsigned char smem_raw[];
    float* spec = reinterpret_cast<float*>(smem_raw);
    int*   meta = reinterpret_cast<int*>(smem_raw + SPEC_BYTES);

    const int tid  = threadIdx.x;
    const int dir  = dir_ptr ? __ldg(dir_ptr) : 0;
    const int gl   = tid >> 1;          // group within tile owned by thread
    const int half = tid & 1;           // 0 -> ions 0..3 (cb), 1 -> ions 4..7 (cy)

    // ---- stage spectrum into SMEM (zero the 16-float pad) ----
    {
        const float4* s4 = reinterpret_cast<const float4*>(spectrum);
        float4*       d4 = reinterpret_cast<float4*>(spec);
        const float4  z4 = make_float4(0.f, 0.f, 0.f, 0.f);
        #pragma unroll 2
        for (int i = tid; i < SPEC_FLOATS_PAD / 4; i += THREADS)
            d4[i] = (i < MAX_MZ / 4) ? s4[i] : z4;
    }

    // ---- prologue: prefetch tile-0 inputs (3 LDGs per thread) ----
    float pm, pf, ms;
    int   v;
    {
        const int g = blockIdx.x * TILE_GROUPS + gl;
        const int b = g / VOCAB;  v = g - b * VOCAB;
        pm = __ldg(pepmass + b); pf = __ldg(prefix_mass + b); ms = __ldg(masses + v);
    }

    int parity = 0;
    for (int tile = blockIdx.x; tile < NUM_TILES; tile += GRID_BLOCKS) {
        int* mb = meta + parity * METABUF;
        parity ^= 1;

        // ---- publish this tile's metadata: 4 windows, one STS.128 ----
        {
            float cb, cy;
            if (dir == 0) { cb = pf + ms; cy = pm - cb; }
            else          { cy = pf + ms; cb = pm - cy; }
            const float c   = half ? cy : cb;
            const bool  vok = (v >= 3);
            int4 mw;
            mw.x = one_meta(c, 0, vok);
            mw.y = one_meta(c, 1, vok);
            mw.z = one_meta(c, 2, vok);
            mw.w = one_meta(c, 3, vok);
            reinterpret_cast<int4*>(mb)[tid] = mw;   // windows 4*tid..4*tid+3
        }

        // ---- issue NEXT tile's 3 loads BEFORE the barrier: their latency
        //      drains while the block convoys through __syncthreads, and the
        //      consumers are only at the next loop top.  (pm/pf/ms/v were
        //      already consumed by the publish above.) ----
        {
            int nt = tile + GRID_BLOCKS;
            if (nt >= NUM_TILES) nt = tile;          // clamp: harmless reload
            const int g = nt * TILE_GROUPS + gl;
            const int b = g / VOCAB;  v = g - b * VOCAB;
            pm = __ldg(pepmass + b); pf = __ldg(prefix_mass + b); ms = __ldg(masses + v);
        }

        __syncthreads();   // (first iteration: also covers spectrum staging)

        // ---------- Phase 2: 20 float2 per thread, staged batches ----------
        // A float2 at even element offset NEVER straddles a window.
        // Stage 1: ABATCH meta LDS -> addr[]      (MLP-10 burst)
        // Stage 2/3: two sub-batches of 5 gathers (MLP-10) + 5 stores.
        float2* out2 = reinterpret_cast<float2*>(out) + tile * VEC2_PER_TILE;

        #pragma unroll
        for (int kk = 0; kk < VEC2_PER_THREAD / ABATCH; ++kk) {
            const int q0 = tid + kk * ABATCH * THREADS;
            int addr[ABATCH];

            #pragma unroll
            for (int j = 0; j < ABATCH; ++j) {
                const int q = q0 + j * THREADS;
                const unsigned win = (unsigned)q / 5u;   // window = (2q)/10
                const int w0 = (q - (int)win * 5) * 2;   // in {0,2,4,6,8}
                addr[j] = mb[win] + w0;                  // LDS.32 meta burst
            }

            #pragma unroll
            for (int h = 0; h < ABATCH / VBATCH; ++h) {
                float2 val[VBATCH];
                #pragma unroll
                for (int j = 0; j < VBATCH; ++j) {
                    const int a = addr[h * VBATCH + j];
                    val[j].x = spec[a];
                    val[j].y = spec[a + 1];
                }
                #pragma unroll
                for (int j = 0; j < VBATCH; ++j) {
                    const int q = q0 + (h * VBATCH + j) * THREADS;
                    __stcs(out2 + q, val[j]);            // streaming STG.64
                }
            }
        }
        // no trailing sync: double-buffered metadata (the barrier above
        // proves all readers of the other buffer finished before rewrite)
    }
}

extern "C" void kernel_launch(void* const* d_in, const int* in_sizes, int n_in,
                              void* d_out, int out_size)
{
    const float* spectrum    = (const float*)d_in[0];
    const float* pepmass     = (const float*)d_in[1];
    const float* prefix_mass = (const float*)d_in[2];
    const float* masses      = (const float*)d_in[3];
    const int*   dir_ptr     = (n_in >= 5) ? (const int*)d_in[4] : nullptr;
    float*       out         = (float*)d_out;

    cudaFuncSetAttribute(intensity_kernel,
                         cudaFuncAttributeMaxDynamicSharedMemorySize, SMEM_BYTES);

    intensity_kernel<<<GRID_BLOCKS, THREADS, SMEM_BYTES>>>(
        pepmass, prefix_mass, masses, spectrum, dir_ptr, out);
}